// round 13
// baseline (speedup 1.0000x reference)
#include <cuda_runtime.h>
#include <cuda_fp16.h>
#include <cstdint>

#define NN 100000
#define NE 1600000
#define DD 128
#define LL 3
#define SCAN_BLOCKS ((NN + 1023) / 1024)   // 98

// ---------------- device scratch ----------------
__device__ __half   g_hA[(size_t)NN * DD];
__device__ __half   g_hB[(size_t)NN * DD];
__device__ __half   g_S[(size_t)NN * DD];       // aggregated features (fp16)
__device__ __half   g_WT[(size_t)LL * DD * DD];  // WT[l][n][k] = (half)W[l][k][n]
__device__ float    g_inv[NN];
__device__ int      g_deg[NN];                  // zeroed at start; re-zeroed by scan
__device__ int      g_bsum[SCAN_BLOCKS];        // value-as-flag; -1 = not ready
__device__ int      g_off[NN + 1];
__device__ int      g_cur[NN];
__device__ int      g_csr[NE];                  // BYTE offsets (src * 256)

// ---------------- setup: emb gather + degree count + wconv + bsum sentinel ----------------
__global__ void k_setup(const int* __restrict__ ann, const float* __restrict__ emb,
                        const int* __restrict__ dst, const float* __restrict__ Ws) {
    int t = blockIdx.x * blockDim.x + threadIdx.x;
    if (t < NN * 32) {
        int v = t >> 5, q = t & 31;
        int a = ann[v];
        float4 val = ((const float4*)emb)[(size_t)a * 32 + q];
        uint2 o;
        __half2 h01 = __floats2half2_rn(val.x, val.y);
        __half2 h23 = __floats2half2_rn(val.z, val.w);
        o.x = *(uint32_t*)&h01; o.y = *(uint32_t*)&h23;
        ((uint2*)g_hA)[t] = o;
    }
    if (t < NE) atomicAdd(&g_deg[dst[t]], 1);
    if (t < LL * DD * DD) {
        int l = t >> 14, r = t & 16383, n = r >> 7, k = r & 127;
        g_WT[t] = __float2half_rn(Ws[l * DD * DD + k * DD + n]);
    }
    if (t < SCAN_BLOCKS) g_bsum[t] = -1;
}

// ---------------- fused scan: block scan + aggregate lookback ----------------
__global__ void __launch_bounds__(1024) k_scan() {
    int t = threadIdx.x, b = blockIdx.x;
    int i = b * 1024 + t;
    int d = (i < NN) ? g_deg[i] : 0;

    int lane = t & 31, w = t >> 5;
    int v = d;
    #pragma unroll
    for (int o = 1; o < 32; o <<= 1) {
        int u = __shfl_up_sync(0xffffffffu, v, o);
        if (lane >= o) v += u;
    }
    __shared__ int ws[32];
    __shared__ int s_off;
    if (t == 0) s_off = 0;
    if (lane == 31) ws[w] = v;
    __syncthreads();
    if (w == 0) {
        int x = ws[lane];
        #pragma unroll
        for (int o = 1; o < 32; o <<= 1) {
            int u = __shfl_up_sync(0xffffffffu, x, o);
            if (lane >= o) x += u;
        }
        ws[lane] = x;
    }
    __syncthreads();
    int incl = v + (w > 0 ? ws[w - 1] : 0);

    if (t == 1023) atomicExch(&g_bsum[b], incl);

    if (t < b) {
        volatile int* p = &g_bsum[t];
        int val;
        do { val = *p; } while (val < 0);
        atomicAdd_block(&s_off, val);
    }
    __syncthreads();
    int off = s_off;

    if (i < NN) {
        int tot = incl + off;
        int ex = tot - d;
        g_off[i] = ex;
        g_cur[i] = ex;
        g_inv[i] = 1.0f / (float)(d + 1);
        g_deg[i] = 0;
        if (i == NN - 1) g_off[NN] = tot;
    }
}

// ---------------- scatter: 8 edges/thread, CSR stores BYTE offsets (src*256) ----------------
__global__ void k_scatter(const int* __restrict__ src, const int* __restrict__ dst) {
    int q = blockIdx.x * blockDim.x + threadIdx.x;
    if (q < NE / 8) {
        int4 d4a = ((const int4*)dst)[q * 2 + 0];
        int4 d4b = ((const int4*)dst)[q * 2 + 1];
        int4 s4a = ((const int4*)src)[q * 2 + 0];
        int4 s4b = ((const int4*)src)[q * 2 + 1];
        int p0 = atomicAdd(&g_cur[d4a.x], 1);
        int p1 = atomicAdd(&g_cur[d4a.y], 1);
        int p2 = atomicAdd(&g_cur[d4a.z], 1);
        int p3 = atomicAdd(&g_cur[d4a.w], 1);
        int p4 = atomicAdd(&g_cur[d4b.x], 1);
        int p5 = atomicAdd(&g_cur[d4b.y], 1);
        int p6 = atomicAdd(&g_cur[d4b.z], 1);
        int p7 = atomicAdd(&g_cur[d4b.w], 1);
        g_csr[p0] = s4a.x << 8;
        g_csr[p1] = s4a.y << 8;
        g_csr[p2] = s4a.z << 8;
        g_csr[p3] = s4a.w << 8;
        g_csr[p4] = s4b.x << 8;
        g_csr[p5] = s4b.y << 8;
        g_csr[p6] = s4b.z << 8;
        g_csr[p7] = s4b.w << 8;
    }
}

// ---------------- SAGE aggregation: 2 nodes/warp, 16 lanes x uint4 per row (R11) ----------
__global__ void __launch_bounds__(256) k_sage(const __half* __restrict__ hin) {
    int gt = blockIdx.x * blockDim.x + threadIdx.x;
    int warp = gt >> 5;
    int hh = (gt >> 4) & 1;       // half-warp id: node selector
    int sub = gt & 15;            // lane within half-warp
    int v = warp * 2 + hh;
    if (v >= NN) return;
    const char* hb = (const char*)hin + sub * 16;

    uint4 sv = *(const uint4*)(hb + (size_t)v * 256);
    float2 s0 = __half22float2(*(__half2*)&sv.x);
    float2 s1 = __half22float2(*(__half2*)&sv.y);
    float2 s2 = __half22float2(*(__half2*)&sv.z);
    float2 s3 = __half22float2(*(__half2*)&sv.w);
    float fa0 = s0.x, fa1 = s0.y, fa2 = s1.x, fa3 = s1.y;
    float fa4 = s2.x, fa5 = s2.y, fa6 = s3.x, fa7 = s3.y;

    int s = g_off[v];
    int n = g_off[v + 1] - s;
    int nmax = max(n, __shfl_xor_sync(0xffffffffu, n, 16));

    __half2 z = __float2half2_rn(0.f);
    __half2 ha0 = z, ha1 = z, ha2 = z, ha3 = z;

    for (int j = 0; j < nmax; j++) {
        int uoff = (j < n) ? __ldg(&g_csr[s + j]) : 0;   // broadcast per half-warp
        uint4 xv = *(const uint4*)(hb + uoff);
        if (j < n) {
            ha0 = __hadd2(ha0, *(__half2*)&xv.x);
            ha1 = __hadd2(ha1, *(__half2*)&xv.y);
            ha2 = __hadd2(ha2, *(__half2*)&xv.z);
            ha3 = __hadd2(ha3, *(__half2*)&xv.w);
        }
        if ((j & 3) == 3) {
            float2 g0 = __half22float2(ha0); fa0 += g0.x; fa1 += g0.y;
            float2 g1 = __half22float2(ha1); fa2 += g1.x; fa3 += g1.y;
            float2 g2 = __half22float2(ha2); fa4 += g2.x; fa5 += g2.y;
            float2 g3 = __half22float2(ha3); fa6 += g3.x; fa7 += g3.y;
            ha0 = z; ha1 = z; ha2 = z; ha3 = z;
        }
    }
    {
        float2 g0 = __half22float2(ha0); fa0 += g0.x; fa1 += g0.y;
        float2 g1 = __half22float2(ha1); fa2 += g1.x; fa3 += g1.y;
        float2 g2 = __half22float2(ha2); fa4 += g2.x; fa5 += g2.y;
        float2 g3 = __half22float2(ha3); fa6 += g3.x; fa7 += g3.y;
    }

    float iv = g_inv[v];
    uint4 r;
    __half2 r0 = __floats2half2_rn(fa0 * iv, fa1 * iv);
    __half2 r1 = __floats2half2_rn(fa2 * iv, fa3 * iv);
    __half2 r2 = __floats2half2_rn(fa4 * iv, fa5 * iv);
    __half2 r3 = __floats2half2_rn(fa6 * iv, fa7 * iv);
    r.x = *(uint32_t*)&r0; r.y = *(uint32_t*)&r1;
    r.z = *(uint32_t*)&r2; r.w = *(uint32_t*)&r3;
    *(uint4*)((char*)g_S + (size_t)v * 256 + sub * 16) = r;
}

// ---------------- fp16 MMA GEMM: hout = relu(S @ W + b); B straight from L2 ----------------
#define HP 136
#define GSMEM (128 * HP * 2)

__global__ void __launch_bounds__(256) k_mma(__half* __restrict__ hout_h,
                                             float* __restrict__ out_f,
                                             const __half* __restrict__ WT,
                                             const float* __restrict__ bias) {
    extern __shared__ __half sm[];
    __half* As = sm;             // [128][HP]
    int tid = threadIdx.x;
    int lane = tid & 31, w = tid >> 5;
    int m0 = blockIdx.x * 128;

    #pragma unroll
    for (int t = 0; t < 8; t++) {
        int q = tid + t * 256;            // 0..2047
        int r = q >> 4, c8 = (q & 15) * 8;
        uint4 av;
        if (m0 + r < NN) av = ((const uint4*)g_S)[(size_t)(m0 + r) * 16 + (q & 15)];
        else             av = make_uint4(0u, 0u, 0u, 0u);
        *(uint4*)&As[r * HP + c8] = av;
    }
    __syncthreads();

    int warp_m = w >> 1;
    int warp_n = w & 1;
    int g = lane >> 2;
    int tg = lane & 3;

    float acc[2][8][4];
    #pragma unroll
    for (int mi = 0; mi < 2; mi++)
        #pragma unroll
        for (int ni = 0; ni < 8; ni++)
            #pragma unroll
            for (int c = 0; c < 4; c++) acc[mi][ni][c] = 0.f;

    #pragma unroll
    for (int kc = 0; kc < 8; kc++) {
        int k0 = kc * 16;
        uint32_t a[2][4];
        #pragma unroll
        for (int mi = 0; mi < 2; mi++) {
            int r = warp_m * 32 + mi * 16 + g;
            a[mi][0] = *(uint32_t*)&As[r * HP + k0 + 2 * tg];
            a[mi][1] = *(uint32_t*)&As[(r + 8) * HP + k0 + 2 * tg];
            a[mi][2] = *(uint32_t*)&As[r * HP + k0 + 2 * tg + 8];
            a[mi][3] = *(uint32_t*)&As[(r + 8) * HP + k0 + 2 * tg + 8];
        }
        #pragma unroll
        for (int ni = 0; ni < 8; ni++) {
            int n = warp_n * 64 + ni * 8 + g;
            uint32_t b0 = __ldg((const uint32_t*)&WT[n * DD + k0 + 2 * tg]);
            uint32_t b1 = __ldg((const uint32_t*)&WT[n * DD + k0 + 2 * tg + 8]);
            #pragma unroll
            for (int mi = 0; mi < 2; mi++) {
                asm volatile(
                    "mma.sync.aligned.m16n8k16.row.col.f32.f16.f16.f32 "
                    "{%0,%1,%2,%3}, {%4,%5,%6,%7}, {%8,%9}, {%0,%1,%2,%3};"
                    : "+f"(acc[mi][ni][0]), "+f"(acc[mi][ni][1]),
                      "+f"(acc[mi][ni][2]), "+f"(acc[mi][ni][3])
                    : "r"(a[mi][0]), "r"(a[mi][1]), "r"(a[mi][2]), "r"(a[mi][3]),
                      "r"(b0), "r"(b1));
            }
        }
    }

    #pragma unroll
    for (int ni = 0; ni < 8; ni++) {
        int col = warp_n * 64 + ni * 8 + 2 * tg;
        float b0 = bias[col], b1 = bias[col + 1];
        #pragma unroll
        for (int mi = 0; mi < 2; mi++) {
            int row = m0 + warp_m * 32 + mi * 16 + g;
            float v00 = fmaxf(acc[mi][ni][0] + b0, 0.f);
            float v01 = fmaxf(acc[mi][ni][1] + b1, 0.f);
            float v10 = fmaxf(acc[mi][ni][2] + b0, 0.f);
            float v11 = fmaxf(acc[mi][ni][3] + b1, 0.f);
            if (out_f) {
                if (row < NN)     { float2 r0 = {v00, v01}; *(float2*)&out_f[(size_t)row * DD + col] = r0; }
                if (row + 8 < NN) { float2 r1 = {v10, v11}; *(float2*)&out_f[(size_t)(row + 8) * DD + col] = r1; }
            } else {
                if (row < NN)     *(__half2*)&hout_h[(size_t)row * DD + col] = __floats2half2_rn(v00, v01);
                if (row + 8 < NN) *(__half2*)&hout_h[(size_t)(row + 8) * DD + col] = __floats2half2_rn(v10, v11);
            }
        }
    }
}

// ---------------- launcher ----------------
extern "C" void kernel_launch(void* const* d_in, const int* in_sizes, int n_in,
                              void* d_out, int out_size) {
    const int*   ann = (const int*)d_in[0];
    const int*   src = (const int*)d_in[1];
    const int*   dst = (const int*)d_in[2];
    const float* emb = (const float*)d_in[3];
    const float* Ws  = (const float*)d_in[4];
    const float* bs  = (const float*)d_in[5];
    float*       out = (float*)d_out;

    cudaFuncSetAttribute(k_mma, cudaFuncAttributeMaxDynamicSharedMemorySize, GSMEM);

    __half* hA; __half* hB; __half* WT;
    cudaGetSymbolAddress((void**)&hA, g_hA);
    cudaGetSymbolAddress((void**)&hB, g_hB);
    cudaGetSymbolAddress((void**)&WT, g_WT);

    int grid = (NN + 127) / 128;           // 782 (mma)
    int sgrid = (NN / 2 * 32 + 255) / 256; // 6250 (sage: 2 nodes/warp)

    k_setup  <<<(NN * 32 + 255) / 256, 256>>>(ann, emb, dst, Ws);  // 1
    k_scan   <<<SCAN_BLOCKS, 1024>>>();                            // 2
    k_scatter<<<(NE / 8 + 255) / 256, 256>>>(src, dst);            // 3
    k_sage   <<<sgrid, 256>>>(hA);                                 // 4 <- profiled slot
    k_mma    <<<grid, 256, GSMEM>>>(hB, nullptr, WT + 0 * DD * DD, bs + 0 * DD);
    k_sage   <<<sgrid, 256>>>(hB);
    k_mma    <<<grid, 256, GSMEM>>>(hA, nullptr, WT + 1 * DD * DD, bs + 1 * DD);
    k_sage   <<<sgrid, 256>>>(hA);
    k_mma    <<<grid, 256, GSMEM>>>(nullptr, out, WT + 2 * DD * DD, bs + 2 * DD);
}

// round 14
// speedup vs baseline: 1.2932x; 1.2932x over previous
#include <cuda_runtime.h>
#include <cuda_fp16.h>
#include <cstdint>

#define NN 100000
#define NE 1600000
#define DD 128
#define LL 3
#define SCAN_BLOCKS ((NN + 1023) / 1024)   // 98

// ---------------- device scratch ----------------
__device__ __half   g_hA[(size_t)NN * DD];
__device__ __half   g_hB[(size_t)NN * DD];
__device__ __half   g_S[(size_t)NN * DD];       // aggregated features (fp16)
__device__ __half   g_WT[(size_t)LL * DD * DD];  // WT[l][n][k] = (half)W[l][k][n]
__device__ float    g_inv[NN];
__device__ int      g_deg[NN];                  // zeroed at start; re-zeroed by scan
__device__ int      g_bsum[SCAN_BLOCKS];        // value-as-flag; -1 = not ready
__device__ int      g_off[NN + 1];
__device__ int      g_cur[NN];
__device__ int      g_csr[NE];                  // BYTE offsets (src * 256)

// ---------------- setup: emb gather + degree count + wconv + bsum sentinel ----------------
__global__ void k_setup(const int* __restrict__ ann, const float* __restrict__ emb,
                        const int* __restrict__ dst, const float* __restrict__ Ws) {
    int t = blockIdx.x * blockDim.x + threadIdx.x;
    if (t < NN * 32) {
        int v = t >> 5, q = t & 31;
        int a = ann[v];
        float4 val = ((const float4*)emb)[(size_t)a * 32 + q];
        uint2 o;
        __half2 h01 = __floats2half2_rn(val.x, val.y);
        __half2 h23 = __floats2half2_rn(val.z, val.w);
        o.x = *(uint32_t*)&h01; o.y = *(uint32_t*)&h23;
        ((uint2*)g_hA)[t] = o;
    }
    if (t < NE) atomicAdd(&g_deg[dst[t]], 1);
    if (t < LL * DD * DD) {
        int l = t >> 14, r = t & 16383, n = r >> 7, k = r & 127;
        g_WT[t] = __float2half_rn(Ws[l * DD * DD + k * DD + n]);
    }
    if (t < SCAN_BLOCKS) g_bsum[t] = -1;
}

// ---------------- fused scan: block scan + aggregate lookback ----------------
__global__ void __launch_bounds__(1024) k_scan() {
    int t = threadIdx.x, b = blockIdx.x;
    int i = b * 1024 + t;
    int d = (i < NN) ? g_deg[i] : 0;

    int lane = t & 31, w = t >> 5;
    int v = d;
    #pragma unroll
    for (int o = 1; o < 32; o <<= 1) {
        int u = __shfl_up_sync(0xffffffffu, v, o);
        if (lane >= o) v += u;
    }
    __shared__ int ws[32];
    __shared__ int s_off;
    if (t == 0) s_off = 0;
    if (lane == 31) ws[w] = v;
    __syncthreads();
    if (w == 0) {
        int x = ws[lane];
        #pragma unroll
        for (int o = 1; o < 32; o <<= 1) {
            int u = __shfl_up_sync(0xffffffffu, x, o);
            if (lane >= o) x += u;
        }
        ws[lane] = x;
    }
    __syncthreads();
    int incl = v + (w > 0 ? ws[w - 1] : 0);

    if (t == 1023) atomicExch(&g_bsum[b], incl);

    if (t < b) {
        volatile int* p = &g_bsum[t];
        int val;
        do { val = *p; } while (val < 0);
        atomicAdd_block(&s_off, val);
    }
    __syncthreads();
    int off = s_off;

    if (i < NN) {
        int tot = incl + off;
        int ex = tot - d;
        g_off[i] = ex;
        g_cur[i] = ex;
        g_inv[i] = 1.0f / (float)(d + 1);
        g_deg[i] = 0;
        if (i == NN - 1) g_off[NN] = tot;
    }
}

// ---------------- scatter: 4 edges/thread, CSR stores BYTE offsets (src*256) ----------------
__global__ void k_scatter(const int* __restrict__ src, const int* __restrict__ dst) {
    int q = blockIdx.x * blockDim.x + threadIdx.x;
    if (q < NE / 4) {
        int4 d4 = ((const int4*)dst)[q];
        int4 s4 = ((const int4*)src)[q];
        int p0 = atomicAdd(&g_cur[d4.x], 1); g_csr[p0] = s4.x << 8;
        int p1 = atomicAdd(&g_cur[d4.y], 1); g_csr[p1] = s4.y << 8;
        int p2 = atomicAdd(&g_cur[d4.z], 1); g_csr[p2] = s4.z << 8;
        int p3 = atomicAdd(&g_cur[d4.w], 1); g_csr[p3] = s4.w << 8;
    }
}

// ---------------- SAGE aggregation: 2 nodes/warp, 16 lanes x uint4 per row (R11) ----------
__global__ void __launch_bounds__(256) k_sage(const __half* __restrict__ hin) {
    int gt = blockIdx.x * blockDim.x + threadIdx.x;
    int warp = gt >> 5;
    int hh = (gt >> 4) & 1;       // half-warp id: node selector
    int sub = gt & 15;            // lane within half-warp
    int v = warp * 2 + hh;
    if (v >= NN) return;
    const char* hb = (const char*)hin + sub * 16;

    uint4 sv = *(const uint4*)(hb + (size_t)v * 256);
    float2 s0 = __half22float2(*(__half2*)&sv.x);
    float2 s1 = __half22float2(*(__half2*)&sv.y);
    float2 s2 = __half22float2(*(__half2*)&sv.z);
    float2 s3 = __half22float2(*(__half2*)&sv.w);
    float fa0 = s0.x, fa1 = s0.y, fa2 = s1.x, fa3 = s1.y;
    float fa4 = s2.x, fa5 = s2.y, fa6 = s3.x, fa7 = s3.y;

    int s = g_off[v];
    int n = g_off[v + 1] - s;
    int nmax = max(n, __shfl_xor_sync(0xffffffffu, n, 16));

    __half2 z = __float2half2_rn(0.f);
    __half2 ha0 = z, ha1 = z, ha2 = z, ha3 = z;

    for (int j = 0; j < nmax; j++) {
        int uoff = (j < n) ? __ldg(&g_csr[s + j]) : 0;   // broadcast per half-warp
        uint4 xv = *(const uint4*)(hb + uoff);
        if (j < n) {
            ha0 = __hadd2(ha0, *(__half2*)&xv.x);
            ha1 = __hadd2(ha1, *(__half2*)&xv.y);
            ha2 = __hadd2(ha2, *(__half2*)&xv.z);
            ha3 = __hadd2(ha3, *(__half2*)&xv.w);
        }
        if ((j & 3) == 3) {
            float2 g0 = __half22float2(ha0); fa0 += g0.x; fa1 += g0.y;
            float2 g1 = __half22float2(ha1); fa2 += g1.x; fa3 += g1.y;
            float2 g2 = __half22float2(ha2); fa4 += g2.x; fa5 += g2.y;
            float2 g3 = __half22float2(ha3); fa6 += g3.x; fa7 += g3.y;
            ha0 = z; ha1 = z; ha2 = z; ha3 = z;
        }
    }
    {
        float2 g0 = __half22float2(ha0); fa0 += g0.x; fa1 += g0.y;
        float2 g1 = __half22float2(ha1); fa2 += g1.x; fa3 += g1.y;
        float2 g2 = __half22float2(ha2); fa4 += g2.x; fa5 += g2.y;
        float2 g3 = __half22float2(ha3); fa6 += g3.x; fa7 += g3.y;
    }

    float iv = g_inv[v];
    uint4 r;
    __half2 r0 = __floats2half2_rn(fa0 * iv, fa1 * iv);
    __half2 r1 = __floats2half2_rn(fa2 * iv, fa3 * iv);
    __half2 r2 = __floats2half2_rn(fa4 * iv, fa5 * iv);
    __half2 r3 = __floats2half2_rn(fa6 * iv, fa7 * iv);
    r.x = *(uint32_t*)&r0; r.y = *(uint32_t*)&r1;
    r.z = *(uint32_t*)&r2; r.w = *(uint32_t*)&r3;
    *(uint4*)((char*)g_S + (size_t)v * 256 + sub * 16) = r;
}

// ---------------- fp16 MMA GEMM, 64-row M tile: hout = relu(S @ W + b) ----------------
// As: [64][HP] (k contiguous); Bs: [128][HP] (k contiguous, = WT rows)
#define HP 136
#define GSMEM ((64 + 128) * HP * 2)

__global__ void __launch_bounds__(256) k_mma(__half* __restrict__ hout_h,
                                             float* __restrict__ out_f,
                                             const __half* __restrict__ WT,
                                             const float* __restrict__ bias) {
    extern __shared__ __half sm[];
    __half* As = sm;            // [64][HP]
    __half* Bs = sm + 64 * HP;  // [128][HP]
    int tid = threadIdx.x;
    int lane = tid & 31, w = tid >> 5;
    int m0 = blockIdx.x * 64;

    // fill A: 1024 uint4 (4 iters), B: 2048 uint4 (8 iters)
    #pragma unroll
    for (int t = 0; t < 4; t++) {
        int q = tid + t * 256;            // 0..1023
        int r = q >> 4, c8 = (q & 15) * 8;
        uint4 av;
        if (m0 + r < NN) av = ((const uint4*)g_S)[(size_t)(m0 + r) * 16 + (q & 15)];
        else             av = make_uint4(0u, 0u, 0u, 0u);
        *(uint4*)&As[r * HP + c8] = av;
    }
    #pragma unroll
    for (int t = 0; t < 8; t++) {
        int q = tid + t * 256;            // 0..2047
        int r = q >> 4, c8 = (q & 15) * 8;
        *(uint4*)&Bs[r * HP + c8] = ((const uint4*)WT)[q];
    }
    __syncthreads();

    int warp_m = w >> 1;          // 0..3 (16-row slices)
    int warp_n = w & 1;           // 0..1 (64-col halves)
    int g = lane >> 2;            // 0..7
    int tg = lane & 3;            // 0..3

    float acc[8][4];
    #pragma unroll
    for (int ni = 0; ni < 8; ni++)
        #pragma unroll
        for (int c = 0; c < 4; c++) acc[ni][c] = 0.f;

    #pragma unroll
    for (int kc = 0; kc < 8; kc++) {
        int k0 = kc * 16;
        int r = warp_m * 16 + g;
        uint32_t a0 = *(uint32_t*)&As[r * HP + k0 + 2 * tg];
        uint32_t a1 = *(uint32_t*)&As[(r + 8) * HP + k0 + 2 * tg];
        uint32_t a2 = *(uint32_t*)&As[r * HP + k0 + 2 * tg + 8];
        uint32_t a3 = *(uint32_t*)&As[(r + 8) * HP + k0 + 2 * tg + 8];
        #pragma unroll
        for (int ni = 0; ni < 8; ni++) {
            int n = warp_n * 64 + ni * 8 + g;
            uint32_t b0 = *(uint32_t*)&Bs[n * HP + k0 + 2 * tg];
            uint32_t b1 = *(uint32_t*)&Bs[n * HP + k0 + 2 * tg + 8];
            asm volatile(
                "mma.sync.aligned.m16n8k16.row.col.f32.f16.f16.f32 "
                "{%0,%1,%2,%3}, {%4,%5,%6,%7}, {%8,%9}, {%0,%1,%2,%3};"
                : "+f"(acc[ni][0]), "+f"(acc[ni][1]),
                  "+f"(acc[ni][2]), "+f"(acc[ni][3])
                : "r"(a0), "r"(a1), "r"(a2), "r"(a3),
                  "r"(b0), "r"(b1));
        }
    }

    #pragma unroll
    for (int ni = 0; ni < 8; ni++) {
        int col = warp_n * 64 + ni * 8 + 2 * tg;
        float b0 = bias[col], b1 = bias[col + 1];
        int row = m0 + warp_m * 16 + g;
        float v00 = fmaxf(acc[ni][0] + b0, 0.f);
        float v01 = fmaxf(acc[ni][1] + b1, 0.f);
        float v10 = fmaxf(acc[ni][2] + b0, 0.f);
        float v11 = fmaxf(acc[ni][3] + b1, 0.f);
        if (out_f) {
            if (row < NN)     { float2 r0 = {v00, v01}; *(float2*)&out_f[(size_t)row * DD + col] = r0; }
            if (row + 8 < NN) { float2 r1 = {v10, v11}; *(float2*)&out_f[(size_t)(row + 8) * DD + col] = r1; }
        } else {
            if (row < NN)     *(__half2*)&hout_h[(size_t)row * DD + col] = __floats2half2_rn(v00, v01);
            if (row + 8 < NN) *(__half2*)&hout_h[(size_t)(row + 8) * DD + col] = __floats2half2_rn(v10, v11);
        }
    }
}

// ---------------- launcher ----------------
extern "C" void kernel_launch(void* const* d_in, const int* in_sizes, int n_in,
                              void* d_out, int out_size) {
    const int*   ann = (const int*)d_in[0];
    const int*   src = (const int*)d_in[1];
    const int*   dst = (const int*)d_in[2];
    const float* emb = (const float*)d_in[3];
    const float* Ws  = (const float*)d_in[4];
    const float* bs  = (const float*)d_in[5];
    float*       out = (float*)d_out;

    cudaFuncSetAttribute(k_mma, cudaFuncAttributeMaxDynamicSharedMemorySize, GSMEM);

    __half* hA; __half* hB; __half* WT;
    cudaGetSymbolAddress((void**)&hA, g_hA);
    cudaGetSymbolAddress((void**)&hB, g_hB);
    cudaGetSymbolAddress((void**)&WT, g_WT);

    int grid = (NN + 63) / 64;             // 1563 (mma, 64-row tiles)
    int sgrid = (NN / 2 * 32 + 255) / 256; // 6250 (sage: 2 nodes/warp)

    k_setup  <<<(NN * 32 + 255) / 256, 256>>>(ann, emb, dst, Ws);  // 1
    k_scan   <<<SCAN_BLOCKS, 1024>>>();                            // 2
    k_scatter<<<(NE / 4 + 255) / 256, 256>>>(src, dst);            // 3
    k_sage   <<<sgrid, 256>>>(hA);                                 // 4 <- profiled slot
    k_mma    <<<grid, 256, GSMEM>>>(hB, nullptr, WT + 0 * DD * DD, bs + 0 * DD);
    k_sage   <<<sgrid, 256>>>(hB);
    k_mma    <<<grid, 256, GSMEM>>>(hA, nullptr, WT + 1 * DD * DD, bs + 1 * DD);
    k_sage   <<<sgrid, 256>>>(hA);
    k_mma    <<<grid, 256, GSMEM>>>(nullptr, out, WT + 2 * DD * DD, bs + 2 * DD);
}

// round 16
// speedup vs baseline: 1.3468x; 1.0415x over previous
#include <cuda_runtime.h>
#include <cuda_fp16.h>
#include <cstdint>

#define NN 100000
#define NE 1600000
#define DD 128
#define LL 3
#define SCAN_BLOCKS ((NN + 1023) / 1024)   // 98

// ---------------- device scratch ----------------
__device__ __half   g_hA[(size_t)NN * DD];
__device__ __half   g_hB[(size_t)NN * DD];
__device__ __half   g_S[(size_t)NN * DD];       // aggregated features (fp16)
__device__ __half   g_WT[(size_t)LL * DD * DD];  // WT[l][n][k] = (half)W[l][k][n]
__device__ float    g_inv[NN];
__device__ int      g_deg[NN];                  // zeroed at start; re-zeroed by scan
__device__ int      g_bsum[SCAN_BLOCKS];        // value-as-flag; -1 = not ready
__device__ int      g_off[NN + 1];
__device__ int      g_cur[NN];
__device__ int      g_csr[NE];                  // BYTE offsets (src * 256)

// ---------------- emb gather (side stream): hA = (half)emb[annotation] ----------------
__global__ void k_emb(const int* __restrict__ ann, const float* __restrict__ emb) {
    int t = blockIdx.x * blockDim.x + threadIdx.x;
    if (t < NN * 32) {
        int v = t >> 5, q = t & 31;
        int a = ann[v];
        float4 val = ((const float4*)emb)[(size_t)a * 32 + q];
        uint2 o;
        __half2 h01 = __floats2half2_rn(val.x, val.y);
        __half2 h23 = __floats2half2_rn(val.z, val.w);
        o.x = *(uint32_t*)&h01; o.y = *(uint32_t*)&h23;
        ((uint2*)g_hA)[t] = o;
    }
}

// ---------------- misc setup (main stream): degree count + wconv + bsum sentinel -------
__global__ void k_misc(const int* __restrict__ dst, const float* __restrict__ Ws) {
    int t = blockIdx.x * blockDim.x + threadIdx.x;
    if (t < NE) atomicAdd(&g_deg[dst[t]], 1);
    if (t < LL * DD * DD) {
        int l = t >> 14, r = t & 16383, n = r >> 7, k = r & 127;
        g_WT[t] = __float2half_rn(Ws[l * DD * DD + k * DD + n]);
    }
    if (t < SCAN_BLOCKS) g_bsum[t] = -1;
}

// ---------------- fused scan: block scan + aggregate lookback ----------------
__global__ void __launch_bounds__(1024) k_scan() {
    int t = threadIdx.x, b = blockIdx.x;
    int i = b * 1024 + t;
    int d = (i < NN) ? g_deg[i] : 0;

    int lane = t & 31, w = t >> 5;
    int v = d;
    #pragma unroll
    for (int o = 1; o < 32; o <<= 1) {
        int u = __shfl_up_sync(0xffffffffu, v, o);
        if (lane >= o) v += u;
    }
    __shared__ int ws[32];
    __shared__ int s_off;
    if (t == 0) s_off = 0;
    if (lane == 31) ws[w] = v;
    __syncthreads();
    if (w == 0) {
        int x = ws[lane];
        #pragma unroll
        for (int o = 1; o < 32; o <<= 1) {
            int u = __shfl_up_sync(0xffffffffu, x, o);
            if (lane >= o) x += u;
        }
        ws[lane] = x;
    }
    __syncthreads();
    int incl = v + (w > 0 ? ws[w - 1] : 0);

    if (t == 1023) atomicExch(&g_bsum[b], incl);

    if (t < b) {
        volatile int* p = &g_bsum[t];
        int val;
        do { val = *p; } while (val < 0);
        atomicAdd_block(&s_off, val);
    }
    __syncthreads();
    int off = s_off;

    if (i < NN) {
        int tot = incl + off;
        int ex = tot - d;
        g_off[i] = ex;
        g_cur[i] = ex;
        g_inv[i] = 1.0f / (float)(d + 1);
        g_deg[i] = 0;
        if (i == NN - 1) g_off[NN] = tot;
    }
}

// ---------------- scatter: 4 edges/thread, CSR stores BYTE offsets (src*256) ----------------
__global__ void k_scatter(const int* __restrict__ src, const int* __restrict__ dst) {
    int q = blockIdx.x * blockDim.x + threadIdx.x;
    if (q < NE / 4) {
        int4 d4 = ((const int4*)dst)[q];
        int4 s4 = ((const int4*)src)[q];
        int p0 = atomicAdd(&g_cur[d4.x], 1); g_csr[p0] = s4.x << 8;
        int p1 = atomicAdd(&g_cur[d4.y], 1); g_csr[p1] = s4.y << 8;
        int p2 = atomicAdd(&g_cur[d4.z], 1); g_csr[p2] = s4.z << 8;
        int p3 = atomicAdd(&g_cur[d4.w], 1); g_csr[p3] = s4.w << 8;
    }
}

// ---------------- SAGE aggregation: 2 nodes/warp, 16 lanes x uint4 per row (R11) ----------
__global__ void __launch_bounds__(256) k_sage(const __half* __restrict__ hin) {
    int gt = blockIdx.x * blockDim.x + threadIdx.x;
    int warp = gt >> 5;
    int hh = (gt >> 4) & 1;       // half-warp id: node selector
    int sub = gt & 15;            // lane within half-warp
    int v = warp * 2 + hh;
    if (v >= NN) return;
    const char* hb = (const char*)hin + sub * 16;

    uint4 sv = *(const uint4*)(hb + (size_t)v * 256);
    float2 s0 = __half22float2(*(__half2*)&sv.x);
    float2 s1 = __half22float2(*(__half2*)&sv.y);
    float2 s2 = __half22float2(*(__half2*)&sv.z);
    float2 s3 = __half22float2(*(__half2*)&sv.w);
    float fa0 = s0.x, fa1 = s0.y, fa2 = s1.x, fa3 = s1.y;
    float fa4 = s2.x, fa5 = s2.y, fa6 = s3.x, fa7 = s3.y;

    int s = g_off[v];
    int n = g_off[v + 1] - s;
    int nmax = max(n, __shfl_xor_sync(0xffffffffu, n, 16));

    __half2 z = __float2half2_rn(0.f);
    __half2 ha0 = z, ha1 = z, ha2 = z, ha3 = z;

    for (int j = 0; j < nmax; j++) {
        int uoff = (j < n) ? __ldg(&g_csr[s + j]) : 0;   // broadcast per half-warp
        uint4 xv = *(const uint4*)(hb + uoff);
        if (j < n) {
            ha0 = __hadd2(ha0, *(__half2*)&xv.x);
            ha1 = __hadd2(ha1, *(__half2*)&xv.y);
            ha2 = __hadd2(ha2, *(__half2*)&xv.z);
            ha3 = __hadd2(ha3, *(__half2*)&xv.w);
        }
        if ((j & 3) == 3) {
            float2 g0 = __half22float2(ha0); fa0 += g0.x; fa1 += g0.y;
            float2 g1 = __half22float2(ha1); fa2 += g1.x; fa3 += g1.y;
            float2 g2 = __half22float2(ha2); fa4 += g2.x; fa5 += g2.y;
            float2 g3 = __half22float2(ha3); fa6 += g3.x; fa7 += g3.y;
            ha0 = z; ha1 = z; ha2 = z; ha3 = z;
        }
    }
    {
        float2 g0 = __half22float2(ha0); fa0 += g0.x; fa1 += g0.y;
        float2 g1 = __half22float2(ha1); fa2 += g1.x; fa3 += g1.y;
        float2 g2 = __half22float2(ha2); fa4 += g2.x; fa5 += g2.y;
        float2 g3 = __half22float2(ha3); fa6 += g3.x; fa7 += g3.y;
    }

    float iv = g_inv[v];
    uint4 r;
    __half2 r0 = __floats2half2_rn(fa0 * iv, fa1 * iv);
    __half2 r1 = __floats2half2_rn(fa2 * iv, fa3 * iv);
    __half2 r2 = __floats2half2_rn(fa4 * iv, fa5 * iv);
    __half2 r3 = __floats2half2_rn(fa6 * iv, fa7 * iv);
    r.x = *(uint32_t*)&r0; r.y = *(uint32_t*)&r1;
    r.z = *(uint32_t*)&r2; r.w = *(uint32_t*)&r3;
    *(uint4*)((char*)g_S + (size_t)v * 256 + sub * 16) = r;
}

// ---------------- fp16 MMA GEMM (R11): hout = relu(S @ W + b) ----------------
#define HP 136
#define GSMEM (2 * 128 * HP * 2)

__global__ void __launch_bounds__(256, 2) k_mma(__half* __restrict__ hout_h,
                                                float* __restrict__ out_f,
                                                const __half* __restrict__ WT,
                                                const float* __restrict__ bias) {
    extern __shared__ __half sm[];
    __half* As = sm;             // [128][HP]
    __half* Bs = sm + 128 * HP;  // [128][HP]
    int tid = threadIdx.x;
    int lane = tid & 31, w = tid >> 5;
    int m0 = blockIdx.x * 128;

    #pragma unroll
    for (int t = 0; t < 8; t++) {
        int q = tid + t * 256;            // 0..2047
        int r = q >> 4, c8 = (q & 15) * 8;
        uint4 av;
        if (m0 + r < NN) av = ((const uint4*)g_S)[(size_t)(m0 + r) * 16 + (q & 15)];
        else             av = make_uint4(0u, 0u, 0u, 0u);
        *(uint4*)&As[r * HP + c8] = av;
        *(uint4*)&Bs[r * HP + c8] = ((const uint4*)WT)[q];
    }
    __syncthreads();

    int warp_m = w >> 1;
    int warp_n = w & 1;
    int g = lane >> 2;
    int tg = lane & 3;

    float acc[2][8][4];
    #pragma unroll
    for (int mi = 0; mi < 2; mi++)
        #pragma unroll
        for (int ni = 0; ni < 8; ni++)
            #pragma unroll
            for (int c = 0; c < 4; c++) acc[mi][ni][c] = 0.f;

    #pragma unroll
    for (int kc = 0; kc < 8; kc++) {
        int k0 = kc * 16;
        uint32_t a[2][4];
        #pragma unroll
        for (int mi = 0; mi < 2; mi++) {
            int r = warp_m * 32 + mi * 16 + g;
            a[mi][0] = *(uint32_t*)&As[r * HP + k0 + 2 * tg];
            a[mi][1] = *(uint32_t*)&As[(r + 8) * HP + k0 + 2 * tg];
            a[mi][2] = *(uint32_t*)&As[r * HP + k0 + 2 * tg + 8];
            a[mi][3] = *(uint32_t*)&As[(r + 8) * HP + k0 + 2 * tg + 8];
        }
        #pragma unroll
        for (int ni = 0; ni < 8; ni++) {
            int n = warp_n * 64 + ni * 8 + g;
            uint32_t b0 = *(uint32_t*)&Bs[n * HP + k0 + 2 * tg];
            uint32_t b1 = *(uint32_t*)&Bs[n * HP + k0 + 2 * tg + 8];
            #pragma unroll
            for (int mi = 0; mi < 2; mi++) {
                asm volatile(
                    "mma.sync.aligned.m16n8k16.row.col.f32.f16.f16.f32 "
                    "{%0,%1,%2,%3}, {%4,%5,%6,%7}, {%8,%9}, {%0,%1,%2,%3};"
                    : "+f"(acc[mi][ni][0]), "+f"(acc[mi][ni][1]),
                      "+f"(acc[mi][ni][2]), "+f"(acc[mi][ni][3])
                    : "r"(a[mi][0]), "r"(a[mi][1]), "r"(a[mi][2]), "r"(a[mi][3]),
                      "r"(b0), "r"(b1));
            }
        }
    }

    #pragma unroll
    for (int ni = 0; ni < 8; ni++) {
        int col = warp_n * 64 + ni * 8 + 2 * tg;
        float b0 = bias[col], b1 = bias[col + 1];
        #pragma unroll
        for (int mi = 0; mi < 2; mi++) {
            int row = m0 + warp_m * 32 + mi * 16 + g;
            float v00 = fmaxf(acc[mi][ni][0] + b0, 0.f);
            float v01 = fmaxf(acc[mi][ni][1] + b1, 0.f);
            float v10 = fmaxf(acc[mi][ni][2] + b0, 0.f);
            float v11 = fmaxf(acc[mi][ni][3] + b1, 0.f);
            if (out_f) {
                if (row < NN)     { float2 r0 = {v00, v01}; *(float2*)&out_f[(size_t)row * DD + col] = r0; }
                if (row + 8 < NN) { float2 r1 = {v10, v11}; *(float2*)&out_f[(size_t)(row + 8) * DD + col] = r1; }
            } else {
                if (row < NN)     *(__half2*)&hout_h[(size_t)row * DD + col] = __floats2half2_rn(v00, v01);
                if (row + 8 < NN) *(__half2*)&hout_h[(size_t)(row + 8) * DD + col] = __floats2half2_rn(v10, v11);
            }
        }
    }
}

// ---------------- launcher: fork emb-gather alongside CSR build ----------------
extern "C" void kernel_launch(void* const* d_in, const int* in_sizes, int n_in,
                              void* d_out, int out_size) {
    const int*   ann = (const int*)d_in[0];
    const int*   src = (const int*)d_in[1];
    const int*   dst = (const int*)d_in[2];
    const float* emb = (const float*)d_in[3];
    const float* Ws  = (const float*)d_in[4];
    const float* bs  = (const float*)d_in[5];
    float*       out = (float*)d_out;

    static cudaStream_t s_side = nullptr;
    static cudaEvent_t  s_ev0 = nullptr, s_ev1 = nullptr;
    if (!s_side) {
        cudaStreamCreateWithFlags(&s_side, cudaStreamNonBlocking);
        cudaEventCreateWithFlags(&s_ev0, cudaEventDisableTiming);
        cudaEventCreateWithFlags(&s_ev1, cudaEventDisableTiming);
    }

    cudaFuncSetAttribute(k_mma, cudaFuncAttributeMaxDynamicSharedMemorySize, GSMEM);

    __half* hA; __half* hB; __half* WT;
    cudaGetSymbolAddress((void**)&hA, g_hA);
    cudaGetSymbolAddress((void**)&hB, g_hB);
    cudaGetSymbolAddress((void**)&WT, g_WT);

    int grid = (NN + 127) / 128;           // 782 (mma)
    int sgrid = (NN / 2 * 32 + 255) / 256; // 6250 (sage: 2 nodes/warp)

    // fork: emb gather on side stream, CSR build on main (legacy) stream
    cudaEventRecord(s_ev0, (cudaStream_t)0);
    cudaStreamWaitEvent(s_side, s_ev0, 0);
    k_emb<<<(NN * 32 + 255) / 256, 256, 0, s_side>>>(ann, emb);

    k_misc   <<<(NE + 255) / 256, 256>>>(dst, Ws);
    k_scan   <<<SCAN_BLOCKS, 1024>>>();
    k_scatter<<<(NE / 4 + 255) / 256, 256>>>(src, dst);

    // join: sage needs both hA (side) and csr (main)
    cudaEventRecord(s_ev1, s_side);
    cudaStreamWaitEvent((cudaStream_t)0, s_ev1, 0);

    k_sage<<<sgrid, 256>>>(hA);
    k_mma <<<grid, 256, GSMEM>>>(hB, nullptr, WT + 0 * DD * DD, bs + 0 * DD);
    k_sage<<<sgrid, 256>>>(hB);
    k_mma <<<grid, 256, GSMEM>>>(hA, nullptr, WT + 1 * DD * DD, bs + 1 * DD);
    k_sage<<<sgrid, 256>>>(hA);
    k_mma <<<grid, 256, GSMEM>>>(nullptr, out, WT + 2 * DD * DD, bs + 2 * DD);
}